// round 7
// baseline (speedup 1.0000x reference)
#include <cuda_runtime.h>

typedef unsigned long long ull;

#define NSEQ 16
#define NTHREADS 288     // 9 warps
#define SEQ_STRIDE 420   // floats per seq in kv; 420 mod 32 = 4 -> conflict-free

__device__ __forceinline__ float ex2f(float x){ float y; asm("ex2.approx.ftz.f32 %0, %1;":"=f"(y):"f"(x)); return y; }
__device__ __forceinline__ float rsqf(float x){ float y; asm("rsqrt.approx.f32 %0, %1;":"=f"(y):"f"(x)); return y; }
__device__ __forceinline__ float rcpf(float x){ float y; asm("rcp.approx.f32 %0, %1;":"=f"(y):"f"(x)); return y; }
__device__ __forceinline__ ull pk(float lo, float hi){ ull r; asm("mov.b64 %0, {%1,%2};":"=l"(r):"f"(lo),"f"(hi)); return r; }
__device__ __forceinline__ void unpk(ull v, float&a, float&b){ asm("mov.b64 {%0,%1}, %2;":"=f"(a),"=f"(b):"l"(v)); }
__device__ __forceinline__ ull f2mul(ull a, ull b){ ull d; asm("mul.rn.f32x2 %0,%1,%2;":"=l"(d):"l"(a),"l"(b)); return d; }
__device__ __forceinline__ ull f2add(ull a, ull b){ ull d; asm("add.rn.f32x2 %0,%1,%2;":"=l"(d):"l"(a),"l"(b)); return d; }
__device__ __forceinline__ ull f2fma(ull a, ull b, ull c){ ull d; asm("fma.rn.f32x2 %0,%1,%2,%3;":"=l"(d):"l"(a),"l"(b),"l"(c)); return d; }

// shared weight buffer layout (floats; pair arrays at even offsets)
#define SW_TOK   0     // 42
#define SW_POS   42    // 102
#define SW_LAYER 144   // 4 x 102
#define LSZ      102
#define O_LNW    0
#define O_LNB    6
#define O_Q      12
#define O_K      30
#define O_V      48
#define O_OUT    66
#define SW_LNF   552
#define SW_LNFB  558
#define SW_HEAD  564   // 84
#define SW_TOTAL 648

__global__ __launch_bounds__(NTHREADS, 2)
void addtrans_kernel(const int* __restrict__ gidx,
                     const float* __restrict__ tok_emb, const float* __restrict__ pos_enc,
                     const float* __restrict__ ln_w,   const float* __restrict__ ln_b,
                     const float* __restrict__ q1w,    const float* __restrict__ k1w, const float* __restrict__ v1w,
                     const float* __restrict__ q2w,    const float* __restrict__ k2w, const float* __restrict__ v2w,
                     const float* __restrict__ out_w,
                     const float* __restrict__ lnf_w,  const float* __restrict__ lnf_b,
                     const float* __restrict__ head_w,
                     float* __restrict__ out)
{
    __shared__ __align__(16) float skv[NSEQ * SEQ_STRIDE];
    __shared__ __align__(16) float sw[SW_TOTAL];
    __shared__ int sidx[NSEQ * 34];

    const int tid = threadIdx.x;
    const float QSCALE = 0.57735026919f * 1.44269504089f; // 1/sqrt(3) * log2(e)

    // ---------------- stage + pre-pack weights ----------------
    if (tid < 42)  sw[SW_TOK + tid] = tok_emb[tid];
    if (tid < 102) sw[SW_POS + tid] = pos_enc[tid];
    if (tid < 24) {
        int l = tid / 6, e = tid % 6, c = e >> 1, h = e & 1;
        sw[SW_LAYER + l*LSZ + O_LNW + e] = ln_w[l*6 + c + h*3];
        sw[SW_LAYER + l*LSZ + O_LNB + e] = ln_b[l*6 + c + h*3];
    }
    if (tid < 72) {
        int l = tid / 18, e = tid % 18, rc = e >> 1, h = e & 1;
        sw[SW_LAYER + l*LSZ + O_Q + e] = (h ? q2w : q1w)[l*9 + rc] * QSCALE;
        sw[SW_LAYER + l*LSZ + O_K + e] = (h ? k2w : k1w)[l*9 + rc];
        sw[SW_LAYER + l*LSZ + O_V + e] = (h ? v2w : v1w)[l*9 + rc];
    }
    if (tid < 144) {
        int l = tid / 36, e = tid % 36, h = e & 1, pr = (e >> 1) % 3, c = e / 6;
        sw[SW_LAYER + l*LSZ + O_OUT + e] = out_w[l*36 + (pr + h*3)*6 + c];
    }
    if (tid < 6) {
        int c = tid >> 1, h = tid & 1;
        sw[SW_LNF  + tid] = lnf_w[c + h*3];
        sw[SW_LNFB + tid] = lnf_b[c + h*3];
    }
    if (tid < 84) {
        int i = tid / 12, rem = tid % 12, c = rem >> 1, h = rem & 1;
        sw[SW_HEAD + tid] = head_w[(2*i + h)*6 + c];
    }
    for (int i = tid; i < NSEQ * 34; i += NTHREADS)
        sidx[i] = gidx[(size_t)blockIdx.x * (NSEQ * 34) + i];
    __syncthreads();

    // ---------------- thread -> (seq, token-pair) mapping ----------------
    const int w = tid >> 5, lane = tid & 31;
    int s, p, trips;
    bool dead = false;
    if (w < 8) {
        s = (w & 1) * 8 + (lane & 7);          // 8 seqs per warp
        p = (w >> 1) * 4 + (lane >> 3);        // pair 0..15
        trips = (w >> 1) * 8 + 8;              // warp-uniform loop bound
    } else {
        dead = (lane >= 16);
        s = lane & 15;
        p = 16;                                 // tokens 32,33
        trips = 34;
    }
    if (dead) return;
    const int t0 = 2 * p, t1 = t0 + 1;

    const int tok0 = sidx[s*34 + t0];
    const int tok1 = sidx[s*34 + t1];

    // residual streams, packed (head1|head2)
    ull xa0 = pk(sw[SW_TOK + tok0*3 + 0], sw[SW_POS + t0*3 + 0]);
    ull xb0 = pk(sw[SW_TOK + tok0*3 + 1], sw[SW_POS + t0*3 + 1]);
    ull xc0 = pk(sw[SW_TOK + tok0*3 + 2], sw[SW_POS + t0*3 + 2]);
    ull xa1 = pk(sw[SW_TOK + tok1*3 + 0], sw[SW_POS + t1*3 + 0]);
    ull xb1 = pk(sw[SW_TOK + tok1*3 + 1], sw[SW_POS + t1*3 + 1]);
    ull xc1 = pk(sw[SW_TOK + tok1*3 + 2], sw[SW_POS + t1*3 + 2]);

    const ulonglong2* kb = (const ulonglong2*)&skv[s * SEQ_STRIDE];
    ulonglong2*      kvw = (ulonglong2*)&skv[s * SEQ_STRIDE + t0 * 12];  // t1 = +3

    const ull neg1 = pk(-1.0f, -1.0f);

    #pragma unroll
    for (int l = 0; l < 4; ++l) {
        const float* LB = &sw[SW_LAYER + l*LSZ];

        // ---- load LN weights once ----
        const ull* LNW = (const ull*)&LB[O_LNW];
        const ull* LNB = (const ull*)&LB[O_LNB];
        ull lw0 = LNW[0], lw1 = LNW[1], lw2 = LNW[2];
        ull lb0 = LNB[0], lb1 = LNB[1], lb2 = LNB[2];

        ull ha0, hb0, hc0, ha1, hb1, hc1;
        {   // LN token0
            float sl_, sh_;
            unpk(f2add(f2add(xa0, xb0), xc0), sl_, sh_);
            float m = (sl_ + sh_) * (1.0f/6.0f);
            ull mm = pk(m, m);
            ull da = f2fma(mm, neg1, xa0), db = f2fma(mm, neg1, xb0), dc = f2fma(mm, neg1, xc0);
            float vl, vh;
            unpk(f2fma(dc, dc, f2fma(db, db, f2mul(da, da))), vl, vh);
            float r = rsqf((vl + vh) * (1.0f/6.0f) + 1e-5f);
            ull rr = pk(r, r);
            ha0 = f2fma(f2mul(da, rr), lw0, lb0);
            hb0 = f2fma(f2mul(db, rr), lw1, lb1);
            hc0 = f2fma(f2mul(dc, rr), lw2, lb2);
        }
        {   // LN token1
            float sl_, sh_;
            unpk(f2add(f2add(xa1, xb1), xc1), sl_, sh_);
            float m = (sl_ + sh_) * (1.0f/6.0f);
            ull mm = pk(m, m);
            ull da = f2fma(mm, neg1, xa1), db = f2fma(mm, neg1, xb1), dc = f2fma(mm, neg1, xc1);
            float vl, vh;
            unpk(f2fma(dc, dc, f2fma(db, db, f2mul(da, da))), vl, vh);
            float r = rsqf((vl + vh) * (1.0f/6.0f) + 1e-5f);
            ull rr = pk(r, r);
            ha1 = f2fma(f2mul(da, rr), lw0, lb0);
            hb1 = f2fma(f2mul(db, rr), lw1, lb1);
            hc1 = f2fma(f2mul(dc, rr), lw2, lb2);
        }

        // ---- Q projection (weights loaded once, used for both tokens) ----
        ull pqx0, pqy0, pqz0, pqx1, pqy1, pqz1;
        {
            const ull* QW = (const ull*)&LB[O_Q];
            ull w0=QW[0],w1=QW[1],w2=QW[2],w3=QW[3],w4=QW[4],w5=QW[5],w6=QW[6],w7=QW[7],w8=QW[8];
            pqx0 = f2fma(hc0, w2, f2fma(hb0, w1, f2mul(ha0, w0)));
            pqy0 = f2fma(hc0, w5, f2fma(hb0, w4, f2mul(ha0, w3)));
            pqz0 = f2fma(hc0, w8, f2fma(hb0, w7, f2mul(ha0, w6)));
            pqx1 = f2fma(hc1, w2, f2fma(hb1, w1, f2mul(ha1, w0)));
            pqy1 = f2fma(hc1, w5, f2fma(hb1, w4, f2mul(ha1, w3)));
            pqz1 = f2fma(hc1, w8, f2fma(hb1, w7, f2mul(ha1, w6)));
        }
        // ---- K projection + store ----
        {
            const ull* KW = (const ull*)&LB[O_K];
            ull w0=KW[0],w1=KW[1],w2=KW[2],w3=KW[3],w4=KW[4],w5=KW[5],w6=KW[6],w7=KW[7],w8=KW[8];
            ull kx0 = f2fma(hc0, w2, f2fma(hb0, w1, f2mul(ha0, w0)));
            ull ky0 = f2fma(hc0, w5, f2fma(hb0, w4, f2mul(ha0, w3)));
            ull kz0 = f2fma(hc0, w8, f2fma(hb0, w7, f2mul(ha0, w6)));
            ull kx1 = f2fma(hc1, w2, f2fma(hb1, w1, f2mul(ha1, w0)));
            ull ky1 = f2fma(hc1, w5, f2fma(hb1, w4, f2mul(ha1, w3)));
            ull kz1 = f2fma(hc1, w8, f2fma(hb1, w7, f2mul(ha1, w6)));
            const ull* VW = (const ull*)&LB[O_V];
            ull u0=VW[0],u1=VW[1],u2=VW[2],u3=VW[3],u4=VW[4],u5=VW[5],u6=VW[6],u7=VW[7],u8=VW[8];
            ull vx0 = f2fma(hc0, u2, f2fma(hb0, u1, f2mul(ha0, u0)));
            ull vy0 = f2fma(hc0, u5, f2fma(hb0, u4, f2mul(ha0, u3)));
            ull vz0 = f2fma(hc0, u8, f2fma(hb0, u7, f2mul(ha0, u6)));
            ull vx1 = f2fma(hc1, u2, f2fma(hb1, u1, f2mul(ha1, u0)));
            ull vy1 = f2fma(hc1, u5, f2fma(hb1, u4, f2mul(ha1, u3)));
            ull vz1 = f2fma(hc1, u8, f2fma(hb1, u7, f2mul(ha1, u6)));
            // layout per token: [kx ky | kz vx | vy vz]
            kvw[0] = make_ulonglong2(kx0, ky0);
            kvw[1] = make_ulonglong2(kz0, vx0);
            kvw[2] = make_ulonglong2(vy0, vz0);
            kvw[3] = make_ulonglong2(kx1, ky1);
            kvw[4] = make_ulonglong2(kz1, vx1);
            kvw[5] = make_ulonglong2(vy1, vz1);
        }
        __syncthreads();

        // ---- causal attention: one KV fetch feeds both tokens ----
        ull den0 = 0ull, ox0 = 0ull, oy0 = 0ull, oz0 = 0ull;
        ull den1 = 0ull, ox1 = 0ull, oy1 = 0ull, oz1 = 0ull;
        const ulonglong2* kp = kb;
        #pragma unroll 2
        for (int j = 0; j < trips; ++j, kp += 3) {
            ulonglong2 A = kp[0];   // kx, ky
            ulonglong2 B = kp[1];   // kz, vx
            ulonglong2 C = kp[2];   // vy, vz
            // token0
            {
                ull ps = f2fma(pqz0, B.x, f2fma(pqy0, A.y, f2mul(pqx0, A.x)));
                float s1, s2; unpk(ps, s1, s2);
                ull pp = pk(ex2f(s1), ex2f(s2));
                pp = (j <= t0) ? pp : 0ull;
                den0 = f2add(den0, pp);
                ox0 = f2fma(pp, B.y, ox0);
                oy0 = f2fma(pp, C.x, oy0);
                oz0 = f2fma(pp, C.y, oz0);
            }
            // token1
            {
                ull ps = f2fma(pqz1, B.x, f2fma(pqy1, A.y, f2mul(pqx1, A.x)));
                float s1, s2; unpk(ps, s1, s2);
                ull pp = pk(ex2f(s1), ex2f(s2));
                pp = (j <= t1) ? pp : 0ull;
                den1 = f2add(den1, pp);
                ox1 = f2fma(pp, B.y, ox1);
                oy1 = f2fma(pp, C.x, oy1);
                oz1 = f2fma(pp, C.y, oz1);
            }
        }
        float d1, d2;
        unpk(den0, d1, d2);  { ull rd = pk(rcpf(d1), rcpf(d2)); ox0 = f2mul(ox0, rd); oy0 = f2mul(oy0, rd); oz0 = f2mul(oz0, rd); }
        unpk(den1, d1, d2);  { ull rd = pk(rcpf(d1), rcpf(d2)); ox1 = f2mul(ox1, rd); oy1 = f2mul(oy1, rd); oz1 = f2mul(oz1, rd); }

        // ---- output projection + residual (weights loaded once) ----
        {
            float a0,a3,a1,a4,a2,a5;
            unpk(ox0,a0,a3); unpk(oy0,a1,a4); unpk(oz0,a2,a5);
            ull c00=pk(a0,a0), c01=pk(a1,a1), c02=pk(a2,a2), c03=pk(a3,a3), c04=pk(a4,a4), c05=pk(a5,a5);
            unpk(ox1,a0,a3); unpk(oy1,a1,a4); unpk(oz1,a2,a5);
            ull c10=pk(a0,a0), c11=pk(a1,a1), c12=pk(a2,a2), c13=pk(a3,a3), c14=pk(a4,a4), c15=pk(a5,a5);
            const ull* OP = (const ull*)&LB[O_OUT];
            #pragma unroll
            for (int c = 0; c < 6; ++c) {
                ull o0 = OP[c*3+0], o1 = OP[c*3+1], o2 = OP[c*3+2];
                ull b0 = (c==0)?c00:(c==1)?c01:(c==2)?c02:(c==3)?c03:(c==4)?c04:c05;
                ull b1 = (c==0)?c10:(c==1)?c11:(c==2)?c12:(c==3)?c13:(c==4)?c14:c15;
                xa0 = f2fma(b0, o0, xa0); xb0 = f2fma(b0, o1, xb0); xc0 = f2fma(b0, o2, xc0);
                xa1 = f2fma(b1, o0, xa1); xb1 = f2fma(b1, o1, xb1); xc1 = f2fma(b1, o2, xc1);
            }
        }
        __syncthreads();   // kv reused next layer
    }

    // ---------------- final LN + head for both tokens ----------------
    const ull* LNF  = (const ull*)&sw[SW_LNF];
    const ull* LNFB = (const ull*)&sw[SW_LNFB];
    ull f0 = LNF[0], f1 = LNF[1], f2_ = LNF[2];
    ull g0_ = LNFB[0], g1_ = LNFB[1], g2_ = LNFB[2];

    ull G[2][6];
    #pragma unroll
    for (int u = 0; u < 2; ++u) {
        ull xa = u ? xa1 : xa0, xb = u ? xb1 : xb0, xc = u ? xc1 : xc0;
        float sl_, sh_;
        unpk(f2add(f2add(xa, xb), xc), sl_, sh_);
        float m = (sl_ + sh_) * (1.0f/6.0f);
        ull mm = pk(m, m);
        ull da = f2fma(mm, neg1, xa), db = f2fma(mm, neg1, xb), dc = f2fma(mm, neg1, xc);
        float vl, vh;
        unpk(f2fma(dc, dc, f2fma(db, db, f2mul(da, da))), vl, vh);
        float r = rsqf((vl + vh) * (1.0f/6.0f) + 1e-5f);
        ull rr = pk(r, r);
        ull ha = f2fma(f2mul(da, rr), f0, g0_);
        ull hb = f2fma(f2mul(db, rr), f1, g1_);
        ull hc = f2fma(f2mul(dc, rr), f2_, g2_);
        float h0,h3,h1,h4,h2,h5;
        unpk(ha,h0,h3); unpk(hb,h1,h4); unpk(hc,h2,h5);
        G[u][0]=pk(h0,h0); G[u][1]=pk(h1,h1); G[u][2]=pk(h2,h2);
        G[u][3]=pk(h3,h3); G[u][4]=pk(h4,h4); G[u][5]=pk(h5,h5);
    }

    const ull* HW = (const ull*)&sw[SW_HEAD];
    size_t base0 = ((size_t)(blockIdx.x * NSEQ + s) * 34 + t0) * 14;
    #pragma unroll
    for (int i = 0; i < 7; ++i) {
        ull w0 = HW[i*6+0], w1 = HW[i*6+1], w2 = HW[i*6+2];
        ull w3 = HW[i*6+3], w4 = HW[i*6+4], w5 = HW[i*6+5];
        ull L0 = f2mul(G[0][0], w0);
        L0 = f2fma(G[0][1], w1, L0); L0 = f2fma(G[0][2], w2, L0);
        L0 = f2fma(G[0][3], w3, L0); L0 = f2fma(G[0][4], w4, L0);
        L0 = f2fma(G[0][5], w5, L0);
        ull L1 = f2mul(G[1][0], w0);
        L1 = f2fma(G[1][1], w1, L1); L1 = f2fma(G[1][2], w2, L1);
        L1 = f2fma(G[1][3], w3, L1); L1 = f2fma(G[1][4], w4, L1);
        L1 = f2fma(G[1][5], w5, L1);
        *(ull*)(out + base0 + 2*i)      = L0;
        *(ull*)(out + base0 + 14 + 2*i) = L1;
    }
}

extern "C" void kernel_launch(void* const* d_in, const int* in_sizes, int n_in,
                              void* d_out, int out_size)
{
    (void)in_sizes; (void)n_in; (void)out_size;
    addtrans_kernel<<<16384 / NSEQ, NTHREADS>>>(
        (const int*)d_in[0],
        (const float*)d_in[1],  (const float*)d_in[2],
        (const float*)d_in[3],  (const float*)d_in[4],
        (const float*)d_in[5],  (const float*)d_in[6],  (const float*)d_in[7],
        (const float*)d_in[8],  (const float*)d_in[9],  (const float*)d_in[10],
        (const float*)d_in[11],
        (const float*)d_in[12], (const float*)d_in[13],
        (const float*)d_in[14],
        (float*)d_out);
}

// round 8
// speedup vs baseline: 1.4077x; 1.4077x over previous
#include <cuda_runtime.h>

typedef unsigned long long ull;

#define NSEQ 16
#define NTHREADS 544     // 17 warps: 16 main (8seq x 4tok) + 1 tail (16seq x 2tok), no dead lanes
#define SEQ_STRIDE 420   // floats per seq in kv; conflict-free for 8-distinct-seq warps

__device__ __forceinline__ float ex2f(float x){ float y; asm("ex2.approx.ftz.f32 %0, %1;":"=f"(y):"f"(x)); return y; }
__device__ __forceinline__ float rsqf(float x){ float y; asm("rsqrt.approx.f32 %0, %1;":"=f"(y):"f"(x)); return y; }
__device__ __forceinline__ float rcpf(float x){ float y; asm("rcp.approx.f32 %0, %1;":"=f"(y):"f"(x)); return y; }
__device__ __forceinline__ ull pk(float lo, float hi){ ull r; asm("mov.b64 %0, {%1,%2};":"=l"(r):"f"(lo),"f"(hi)); return r; }
__device__ __forceinline__ void unpk(ull v, float&a, float&b){ asm("mov.b64 {%0,%1}, %2;":"=f"(a),"=f"(b):"l"(v)); }
__device__ __forceinline__ ull f2mul(ull a, ull b){ ull d; asm("mul.rn.f32x2 %0,%1,%2;":"=l"(d):"l"(a),"l"(b)); return d; }
__device__ __forceinline__ ull f2add(ull a, ull b){ ull d; asm("add.rn.f32x2 %0,%1,%2;":"=l"(d):"l"(a),"l"(b)); return d; }
__device__ __forceinline__ ull f2fma(ull a, ull b, ull c){ ull d; asm("fma.rn.f32x2 %0,%1,%2,%3;":"=l"(d):"l"(a),"l"(b),"l"(c)); return d; }

// shared weight buffer layout (floats; pair arrays at even offsets)
#define SW_TOK   0     // 42
#define SW_POS   42    // 102
#define SW_LAYER 144   // 4 x 102
#define LSZ      102
#define O_LNW    0
#define O_LNB    6
#define O_Q      12
#define O_K      30
#define O_V      48
#define O_OUT    66
#define SW_LNF   552
#define SW_LNFB  558
#define SW_HEAD  564   // 84
#define SW_TOTAL 648

__global__ __launch_bounds__(NTHREADS, 2)
void addtrans_kernel(const int* __restrict__ gidx,
                     const float* __restrict__ tok_emb, const float* __restrict__ pos_enc,
                     const float* __restrict__ ln_w,   const float* __restrict__ ln_b,
                     const float* __restrict__ q1w,    const float* __restrict__ k1w, const float* __restrict__ v1w,
                     const float* __restrict__ q2w,    const float* __restrict__ k2w, const float* __restrict__ v2w,
                     const float* __restrict__ out_w,
                     const float* __restrict__ lnf_w,  const float* __restrict__ lnf_b,
                     const float* __restrict__ head_w,
                     float* __restrict__ out)
{
    __shared__ __align__(16) float skv[NSEQ * SEQ_STRIDE];
    __shared__ __align__(16) float sw[SW_TOTAL];
    __shared__ int sidx[NSEQ * 34];

    const int tid = threadIdx.x;
    const float QSCALE = 0.57735026919f * 1.44269504089f; // 1/sqrt(3) * log2(e)

    // ---------------- stage + pre-pack weights ----------------
    if (tid < 42)  sw[SW_TOK + tid] = tok_emb[tid];
    if (tid < 102) sw[SW_POS + tid] = pos_enc[tid];
    if (tid < 24) {
        int l = tid / 6, e = tid % 6, c = e >> 1, h = e & 1;
        sw[SW_LAYER + l*LSZ + O_LNW + e] = ln_w[l*6 + c + h*3];
        sw[SW_LAYER + l*LSZ + O_LNB + e] = ln_b[l*6 + c + h*3];
    }
    if (tid < 72) {
        int l = tid / 18, e = tid % 18, rc = e >> 1, h = e & 1;
        sw[SW_LAYER + l*LSZ + O_Q + e] = (h ? q2w : q1w)[l*9 + rc] * QSCALE;
        sw[SW_LAYER + l*LSZ + O_K + e] = (h ? k2w : k1w)[l*9 + rc];
        sw[SW_LAYER + l*LSZ + O_V + e] = (h ? v2w : v1w)[l*9 + rc];
    }
    if (tid < 144) {
        int l = tid / 36, e = tid % 36, h = e & 1, pr = (e >> 1) % 3, c = e / 6;
        sw[SW_LAYER + l*LSZ + O_OUT + e] = out_w[l*36 + (pr + h*3)*6 + c];
    }
    if (tid < 6) {
        int c = tid >> 1, h = tid & 1;
        sw[SW_LNF  + tid] = lnf_w[c + h*3];
        sw[SW_LNFB + tid] = lnf_b[c + h*3];
    }
    if (tid < 84) {
        int i = tid / 12, rem = tid % 12, c = rem >> 1, h = rem & 1;
        sw[SW_HEAD + tid] = head_w[(2*i + h)*6 + c];
    }
    sidx[tid] = gidx[(size_t)blockIdx.x * (NSEQ * 34) + tid];   // 544 = 16*34 exactly
    __syncthreads();

    // ---------------- thread -> (seq, token) mapping ----------------
    const int w = tid >> 5, lane = tid & 31;
    int s, t, trips;
    if (w < 16) {
        int g = w & 7;                      // token group
        s = (w >> 3) * 8 + (lane & 7);      // seq-half x 8 seqs
        t = 4 * g + (lane >> 3);
        trips = 4 * g + 4;                  // warp-uniform
    } else {                                // tail: 16 seqs x tokens {32,33}, full warp
        s = lane & 15;
        t = 32 + (lane >> 4);
        trips = 34;
    }

    const int token = sidx[s * 34 + t];

    // residual stream, packed (head1|head2): xa=(x0,x3) xb=(x1,x4) xc=(x2,x5)
    ull xa = pk(sw[SW_TOK + token*3 + 0], sw[SW_POS + t*3 + 0]);
    ull xb = pk(sw[SW_TOK + token*3 + 1], sw[SW_POS + t*3 + 1]);
    ull xc = pk(sw[SW_TOK + token*3 + 2], sw[SW_POS + t*3 + 2]);

    const ulonglong2* kb = (const ulonglong2*)&skv[s * SEQ_STRIDE];
    ulonglong2*      kvw = (ulonglong2*)&skv[s * SEQ_STRIDE + t * 12];

    #pragma unroll
    for (int l = 0; l < 4; ++l) {
        const float* LB = &sw[SW_LAYER + l*LSZ];

        // ---- layernorm (packed) ----
        float sl_, sh_;
        unpk(f2add(f2add(xa, xb), xc), sl_, sh_);
        float m = (sl_ + sh_) * (1.0f / 6.0f);
        ull mm = pk(m, m);
        ull neg1 = pk(-1.0f, -1.0f);
        ull da = f2fma(mm, neg1, xa);
        ull db = f2fma(mm, neg1, xb);
        ull dc = f2fma(mm, neg1, xc);
        float vl, vh;
        unpk(f2fma(dc, dc, f2fma(db, db, f2mul(da, da))), vl, vh);
        float r = rsqf((vl + vh) * (1.0f / 6.0f) + 1e-5f);
        ull rr = pk(r, r);
        const ull* LNW = (const ull*)&LB[O_LNW];
        const ull* LNB = (const ull*)&LB[O_LNB];
        ull ha = f2fma(f2mul(da, rr), LNW[0], LNB[0]);
        ull hb = f2fma(f2mul(db, rr), LNW[1], LNB[1]);
        ull hc = f2fma(f2mul(dc, rr), LNW[2], LNB[2]);

        // ---- projections (packed over both heads) ----
        const ull* QW = (const ull*)&LB[O_Q];
        const ull* KW = (const ull*)&LB[O_K];
        const ull* VW = (const ull*)&LB[O_V];
        ull pqx = f2fma(hc, QW[2], f2fma(hb, QW[1], f2mul(ha, QW[0])));
        ull pqy = f2fma(hc, QW[5], f2fma(hb, QW[4], f2mul(ha, QW[3])));
        ull pqz = f2fma(hc, QW[8], f2fma(hb, QW[7], f2mul(ha, QW[6])));
        ull pkx = f2fma(hc, KW[2], f2fma(hb, KW[1], f2mul(ha, KW[0])));
        ull pky = f2fma(hc, KW[5], f2fma(hb, KW[4], f2mul(ha, KW[3])));
        ull pkz = f2fma(hc, KW[8], f2fma(hb, KW[7], f2mul(ha, KW[6])));
        ull pvx = f2fma(hc, VW[2], f2fma(hb, VW[1], f2mul(ha, VW[0])));
        ull pvy = f2fma(hc, VW[5], f2fma(hb, VW[4], f2mul(ha, VW[3])));
        ull pvz = f2fma(hc, VW[8], f2fma(hb, VW[7], f2mul(ha, VW[6])));

        // ---- publish packed k/v: [kx ky | kz vx | vy vz] ----
        kvw[0] = make_ulonglong2(pkx, pky);
        kvw[1] = make_ulonglong2(pkz, pvx);
        kvw[2] = make_ulonglong2(pvy, pvz);
        __syncthreads();

        // ---- causal attention, both heads packed ----
        ull pden = 0ull, pox = 0ull, poy = 0ull, poz = 0ull;
        const ulonglong2* kp = kb;
        #pragma unroll 2
        for (int j = 0; j < trips; ++j, kp += 3) {
            ulonglong2 A = kp[0];
            ulonglong2 B = kp[1];
            ulonglong2 C = kp[2];
            ull ps = f2fma(pqz, B.x, f2fma(pqy, A.y, f2mul(pqx, A.x)));
            float s1, s2; unpk(ps, s1, s2);
            ull pp = pk(ex2f(s1), ex2f(s2));
            pp = (j <= t) ? pp : 0ull;          // causal mask
            pden = f2add(pden, pp);
            pox = f2fma(pp, B.y, pox);
            poy = f2fma(pp, C.x, poy);
            poz = f2fma(pp, C.y, poz);
        }
        float d1, d2; unpk(pden, d1, d2);
        ull prd = pk(rcpf(d1), rcpf(d2));
        pox = f2mul(pox, prd);
        poy = f2mul(poy, prd);
        poz = f2mul(poz, prd);

        // ---- output projection + residual ----
        float o0, o3, o1, o4, o2, o5;
        unpk(pox, o0, o3); unpk(poy, o1, o4); unpk(poz, o2, o5);
        ull b0 = pk(o0, o0), b1 = pk(o1, o1), b2 = pk(o2, o2);
        ull b3 = pk(o3, o3), b4 = pk(o4, o4), b5 = pk(o5, o5);
        const ull* OP = (const ull*)&LB[O_OUT];   // OP[c*3 + pr]
        xa = f2fma(b0, OP[0],  xa); xb = f2fma(b0, OP[1],  xb); xc = f2fma(b0, OP[2],  xc);
        xa = f2fma(b1, OP[3],  xa); xb = f2fma(b1, OP[4],  xb); xc = f2fma(b1, OP[5],  xc);
        xa = f2fma(b2, OP[6],  xa); xb = f2fma(b2, OP[7],  xb); xc = f2fma(b2, OP[8],  xc);
        xa = f2fma(b3, OP[9],  xa); xb = f2fma(b3, OP[10], xb); xc = f2fma(b3, OP[11], xc);
        xa = f2fma(b4, OP[12], xa); xb = f2fma(b4, OP[13], xb); xc = f2fma(b4, OP[14], xc);
        xa = f2fma(b5, OP[15], xa); xb = f2fma(b5, OP[16], xb); xc = f2fma(b5, OP[17], xc);

        __syncthreads();   // kv buffer reused next layer
    }

    // ---------------- final layernorm (packed) ----------------
    float sl_, sh_;
    unpk(f2add(f2add(xa, xb), xc), sl_, sh_);
    float m = (sl_ + sh_) * (1.0f / 6.0f);
    ull mm = pk(m, m);
    ull neg1 = pk(-1.0f, -1.0f);
    ull da = f2fma(mm, neg1, xa);
    ull db = f2fma(mm, neg1, xb);
    ull dc = f2fma(mm, neg1, xc);
    float vl, vh;
    unpk(f2fma(dc, dc, f2fma(db, db, f2mul(da, da))), vl, vh);
    float r = rsqf((vl + vh) * (1.0f / 6.0f) + 1e-5f);
    ull rr = pk(r, r);
    const ull* LNF  = (const ull*)&sw[SW_LNF];
    const ull* LNFB = (const ull*)&sw[SW_LNFB];
    ull ha = f2fma(f2mul(da, rr), LNF[0], LNFB[0]);
    ull hb = f2fma(f2mul(db, rr), LNF[1], LNFB[1]);
    ull hc = f2fma(f2mul(dc, rr), LNF[2], LNFB[2]);

    // h broadcasts for head matvec
    float h0, h3, h1, h4, h2, h5;
    unpk(ha, h0, h3); unpk(hb, h1, h4); unpk(hc, h2, h5);
    ull g0 = pk(h0, h0), g1 = pk(h1, h1), g2 = pk(h2, h2);
    ull g3 = pk(h3, h3), g4 = pk(h4, h4), g5 = pk(h5, h5);

    const ull* HW = (const ull*)&sw[SW_HEAD];   // HW[i*6 + c]
    size_t base = ((size_t)(blockIdx.x * NSEQ + s) * 34 + t) * 14;
    #pragma unroll
    for (int i = 0; i < 7; ++i) {
        ull L = f2mul(g0, HW[i*6 + 0]);
        L = f2fma(g1, HW[i*6 + 1], L);
        L = f2fma(g2, HW[i*6 + 2], L);
        L = f2fma(g3, HW[i*6 + 3], L);
        L = f2fma(g4, HW[i*6 + 4], L);
        L = f2fma(g5, HW[i*6 + 5], L);
        *(ull*)(out + base + 2*i) = L;
    }
}

extern "C" void kernel_launch(void* const* d_in, const int* in_sizes, int n_in,
                              void* d_out, int out_size)
{
    (void)in_sizes; (void)n_in; (void)out_size;
    addtrans_kernel<<<16384 / NSEQ, NTHREADS>>>(
        (const int*)d_in[0],
        (const float*)d_in[1],  (const float*)d_in[2],
        (const float*)d_in[3],  (const float*)d_in[4],
        (const float*)d_in[5],  (const float*)d_in[6],  (const float*)d_in[7],
        (const float*)d_in[8],  (const float*)d_in[9],  (const float*)d_in[10],
        (const float*)d_in[11],
        (const float*)d_in[12], (const float*)d_in[13],
        (const float*)d_in[14],
        (float*)d_out);
}